// round 2
// baseline (speedup 1.0000x reference)
#include <cuda_runtime.h>
#include <mma.h>

using namespace nvcuda;

#define BSZ 256
#define SLEN 64
#define HDIM 512
#define H2D 1024
#define VDIM 32000
#define NROWS (BSZ * SLEN) /* 16384 */

// ---------------- device scratch (static, no allocations) ----------------
__device__ float d_E[(size_t)NROWS * HDIM];          // embeddings (rounded), (B*S, H)
__device__ float d_Gft[(size_t)4 * HDIM * NROWS];    // fwd preacts TRANSPOSED [2048][16384]
__device__ float d_Gbt[(size_t)4 * HDIM * NROWS];    // bwd preacts TRANSPOSED
__device__ float d_CombIn[(size_t)NROWS * H2D];      // [hf | hb] per (t,b), rounded
__device__ float d_Gct[(size_t)4 * H2D * NROWS];     // combiner preacts TRANSPOSED [4096][16384]
__device__ float d_h[2][2][BSZ * HDIM];              // [dir][parity], rounded
__device__ float d_cfb[2][BSZ * HDIM];               // [dir], fp32
__device__ float d_hcb[2][BSZ * H2D];                // combiner h [parity], rounded
__device__ float d_cc[BSZ * H2D];                    // fp32
__device__ float d_hcfull[BSZ * H2D];                // final combiner h, FULL fp32 (for head)
__device__ float d_WihFr[4 * HDIM * HDIM];           // rounded weights for projections
__device__ float d_WihBr[4 * HDIM * HDIM];
__device__ float d_WihCr[(size_t)4 * H2D * H2D];

// grid barrier state (zero-initialized; count returns to 0 after every use)
__device__ unsigned g_cnt;
__device__ unsigned g_gen;

// round-to-nearest-even into tf32 (10 explicit mantissa bits)
__device__ __forceinline__ float t32(float x) {
    unsigned u = __float_as_uint(x);
    unsigned r = (u + 0xFFFu + ((u >> 13) & 1u)) & 0xFFFFE000u;
    return __uint_as_float(r);
}
__device__ __forceinline__ float sigm(float x) { return 1.f / (1.f + __expf(-x)); }

__device__ __forceinline__ void cp16(void* dst, const void* src) {
    unsigned d = (unsigned)__cvta_generic_to_shared(dst);
    asm volatile("cp.async.cg.shared.global [%0], [%1], 16;" ::"r"(d), "l"(src));
}
__device__ __forceinline__ void cp_commit() { asm volatile("cp.async.commit_group;"); }
template <int N>
__device__ __forceinline__ void cp_wait() { asm volatile("cp.async.wait_group %0;" ::"n"(N)); }

__device__ __forceinline__ void grid_sync(unsigned nb) {
    __syncthreads();
    if (threadIdx.x == 0) {
        __threadfence();
        unsigned gen = ((volatile unsigned*)&g_gen)[0];
        unsigned t = atomicAdd(&g_cnt, 1u);
        if (t == nb - 1) {
            g_cnt = 0;
            __threadfence();
            atomicExch(&g_gen, gen + 1);
        } else {
            while (((volatile unsigned*)&g_gen)[0] == gen) { __nanosleep(32); }
        }
        __threadfence();
    }
    __syncthreads();
}

// ---------------- small prep kernels ----------------
__global__ void roundcopy_kernel(float* __restrict__ dst, const float* __restrict__ src, int n4) {
    int i = blockIdx.x * 256 + threadIdx.x;
    if (i < n4) {
        float4 v = ((const float4*)src)[i];
        v.x = t32(v.x); v.y = t32(v.y); v.z = t32(v.z); v.w = t32(v.w);
        ((float4*)dst)[i] = v;
    }
}

__global__ void embed_kernel(const int* __restrict__ x, const float* __restrict__ Wemb) {
    int r = blockIdx.x;
    int tok = x[r];
    float4* dst = (float4*)(d_E + (size_t)r * HDIM);
    if (tok == 0) {
        float4 z = {0.f, 0.f, 0.f, 0.f};
        dst[threadIdx.x] = z;
    } else {
        float4 v = ((const float4*)(Wemb + (size_t)tok * HDIM))[threadIdx.x];
        v.x = t32(v.x); v.y = t32(v.y); v.z = t32(v.z); v.w = t32(v.w);
        dst[threadIdx.x] = v;
    }
}

// ---------------- TF32 GEMM on PRE-ROUNDED operands, cp.async double-buffered ----------
// C[M,N] = A[M,K] @ W[N,K]^T. block tile 128x128, BK=32, 256 threads (8 warps 4x2)
__global__ void __launch_bounds__(256) gemm_pre(const float* __restrict__ A,
                                                const float* __restrict__ W,
                                                float* __restrict__ C,
                                                int M, int N, int K) {
    extern __shared__ float sm[];
    float* As = sm;                 // [2][128][36]
    float* Bs = sm + 2 * 128 * 36;  // [2][128][36]
    const int m0 = blockIdx.y * 128, n0 = blockIdx.x * 128;
    const int tid = threadIdx.x;
    const int w = tid >> 5, wm = w >> 1, wn = w & 1;
    const int KT = K >> 5;

    wmma::fragment<wmma::accumulator, 16, 16, 8, float> cf[2][4];
#pragma unroll
    for (int i = 0; i < 2; i++)
#pragma unroll
        for (int j = 0; j < 4; j++) wmma::fill_fragment(cf[i][j], 0.f);

    // prologue prefetch kt=0
    {
#pragma unroll
        for (int i = 0; i < 4; i++) {
            int lin = tid + i * 256;
            int r = lin >> 3, c4 = (lin & 7) * 4;
            cp16(As + r * 36 + c4, A + (size_t)(m0 + r) * K + c4);
            cp16(Bs + r * 36 + c4, W + (size_t)(n0 + r) * K + c4);
        }
        cp_commit();
    }
    int buf = 0;
#pragma unroll 1
    for (int kt = 0; kt < KT; kt++) {
        if (kt + 1 < KT) {
            int nb = buf ^ 1;
#pragma unroll
            for (int i = 0; i < 4; i++) {
                int lin = tid + i * 256;
                int r = lin >> 3, c4 = (lin & 7) * 4;
                cp16(As + nb * 4608 + r * 36 + c4, A + (size_t)(m0 + r) * K + (kt + 1) * 32 + c4);
                cp16(Bs + nb * 4608 + r * 36 + c4, W + (size_t)(n0 + r) * K + (kt + 1) * 32 + c4);
            }
            cp_commit();
            cp_wait<1>();
        } else {
            cp_wait<0>();
        }
        __syncthreads();
#pragma unroll
        for (int ks = 0; ks < 4; ks++) {
            wmma::fragment<wmma::matrix_a, 16, 16, 8, wmma::precision::tf32, wmma::row_major> af[2];
            wmma::fragment<wmma::matrix_b, 16, 16, 8, wmma::precision::tf32, wmma::col_major> bf[4];
#pragma unroll
            for (int i = 0; i < 2; i++)
                wmma::load_matrix_sync(af[i], As + buf * 4608 + (wm * 32 + i * 16) * 36 + ks * 8, 36);
#pragma unroll
            for (int j = 0; j < 4; j++)
                wmma::load_matrix_sync(bf[j], Bs + buf * 4608 + (wn * 64 + j * 16) * 36 + ks * 8, 36);
#pragma unroll
            for (int i = 0; i < 2; i++)
#pragma unroll
                for (int j = 0; j < 4; j++) wmma::mma_sync(cf[i][j], af[i], bf[j], cf[i][j]);
        }
        __syncthreads();
        buf ^= 1;
    }
#pragma unroll
    for (int i = 0; i < 2; i++)
#pragma unroll
        for (int j = 0; j < 4; j++)
            wmma::store_matrix_sync(C + (size_t)(m0 + wm * 32 + i * 16) * N + n0 + wn * 64 + j * 16,
                                    cf[i][j], N, wmma::mem_row_major);
}

// ---------------- PERSISTENT fwd+bwd recurrence ----------------
// 128 blocks = 2 dirs x 64 hidden-col slices (8 cols each). Whh slice resident in smem.
__global__ void __launch_bounds__(256) lstm_fb_persist(
    const float* __restrict__ WhhF, const float* __restrict__ WhhB,
    const float* __restrict__ biF, const float* __restrict__ bhF,
    const float* __restrict__ biB, const float* __restrict__ bhB) {
    extern __shared__ float sm[];
    float* Wt = sm;                  // [16][32][36] tiles
    float* As = sm + 16 * 32 * 36;   // [2][256][36]
    float* gbuf = As;                // overlay [256][36] (after K loop)

    const int dir = blockIdx.x >> 6;
    const int j0 = (blockIdx.x & 63) * 8;
    const int tid = threadIdx.x;
    const int wm = tid >> 5;
    const float* Whh = dir ? WhhB : WhhF;
    const float* bi = dir ? biB : biF;
    const float* bh = dir ? bhB : bhF;
    const float* Gt = dir ? d_Gbt : d_Gft;

    // preload weights: 32 gate rows x 512, rounded, tiled per-k-chunk
#pragma unroll 1
    for (int i = 0; i < 16; i++) {
        int lin4 = i * 256 + tid;      // 4096 float4
        int r = lin4 >> 7;             // 128 float4 per row
        int c4 = (lin4 & 127) * 4;
        int gr = (r >> 3) * HDIM + j0 + (r & 7);
        float4 v = *(const float4*)(Whh + (size_t)gr * HDIM + c4);
        v.x = t32(v.x); v.y = t32(v.y); v.z = t32(v.z); v.w = t32(v.w);
        *(float4*)(Wt + (c4 >> 5) * 1152 + r * 36 + (c4 & 31)) = v;
    }
    const int jj = tid >> 5;    // 0..7 hidden col within slice
    const int brow = tid & 31;
    float bsum[4];
    const float* gp[4];
#pragma unroll
    for (int g = 0; g < 4; g++) {
        bsum[g] = bi[g * HDIM + j0 + jj] + bh[g * HDIM + j0 + jj];
        gp[g] = Gt + (size_t)(g * HDIM + j0 + jj) * NROWS;
    }
    float* cstate = d_cfb[dir];
    __syncthreads();

#pragma unroll 1
    for (int t = 0; t < SLEN; t++) {
        const float* hprev = d_h[dir][t & 1];
        float* hnext = d_h[dir][(t + 1) & 1];
        const int grow0 = (dir ? (SLEN - 1 - t) : t) * BSZ;

        wmma::fragment<wmma::accumulator, 16, 16, 8, float> cf[2][2];
#pragma unroll
        for (int i = 0; i < 2; i++)
#pragma unroll
            for (int j = 0; j < 2; j++) wmma::fill_fragment(cf[i][j], 0.f);

        // prologue prefetch chunk 0 (A = h_prev 256x32)
        {
#pragma unroll
            for (int i = 0; i < 8; i++) {
                int lin4 = i * 256 + tid;
                int r = lin4 >> 3, c4 = (lin4 & 7) * 4;
                cp16(As + r * 36 + c4, hprev + (size_t)r * HDIM + c4);
            }
            cp_commit();
        }
        int buf = 0;
#pragma unroll 1
        for (int kt = 0; kt < 16; kt++) {
            if (kt < 15) {
                int nb = buf ^ 1;
#pragma unroll
                for (int i = 0; i < 8; i++) {
                    int lin4 = i * 256 + tid;
                    int r = lin4 >> 3, c4 = (lin4 & 7) * 4;
                    cp16(As + nb * 9216 + r * 36 + c4,
                         hprev + (size_t)r * HDIM + (kt + 1) * 32 + c4);
                }
                cp_commit();
                cp_wait<1>();
            } else {
                cp_wait<0>();
            }
            __syncthreads();
#pragma unroll
            for (int ks = 0; ks < 4; ks++) {
                wmma::fragment<wmma::matrix_a, 16, 16, 8, wmma::precision::tf32, wmma::row_major> af[2];
                wmma::fragment<wmma::matrix_b, 16, 16, 8, wmma::precision::tf32, wmma::col_major> bf[2];
#pragma unroll
                for (int i = 0; i < 2; i++)
                    wmma::load_matrix_sync(af[i], As + buf * 9216 + (wm * 32 + i * 16) * 36 + ks * 8, 36);
#pragma unroll
                for (int j = 0; j < 2; j++)
                    wmma::load_matrix_sync(bf[j], Wt + kt * 1152 + (j * 16) * 36 + ks * 8, 36);
#pragma unroll
                for (int i = 0; i < 2; i++)
#pragma unroll
                    for (int j = 0; j < 2; j++) wmma::mma_sync(cf[i][j], af[i], bf[j], cf[i][j]);
            }
            __syncthreads();
            buf ^= 1;
        }
        // stage gate preacts (overlay As — safe after final sync)
#pragma unroll
        for (int i = 0; i < 2; i++)
#pragma unroll
            for (int j = 0; j < 2; j++)
                wmma::store_matrix_sync(gbuf + (wm * 32 + i * 16) * 36 + j * 16, cf[i][j], 36,
                                        wmma::mem_row_major);
        __syncthreads();
        // epilogue: coalesced G reads, cell update, rounded h writes
#pragma unroll
        for (int p = 0; p < 8; p++) {
            int b = p * 32 + brow;
            float gi = gbuf[b * 36 + jj]      + gp[0][grow0 + b] + bsum[0];
            float gf = gbuf[b * 36 + 8 + jj]  + gp[1][grow0 + b] + bsum[1];
            float gg = gbuf[b * 36 + 16 + jj] + gp[2][grow0 + b] + bsum[2];
            float go = gbuf[b * 36 + 24 + jj] + gp[3][grow0 + b] + bsum[3];
            float* cp_ = cstate + (size_t)b * HDIM + j0 + jj;
            float cn = sigm(gf) * cp_[0] + sigm(gi) * tanhf(gg);
            cp_[0] = cn;
            float hr = t32(sigm(go) * tanhf(cn));
            hnext[(size_t)b * HDIM + j0 + jj] = hr;
            d_CombIn[(size_t)(t * BSZ + b) * H2D + dir * HDIM + j0 + jj] = hr;
        }
        if (t < SLEN - 1) grid_sync(128);
    }
}

// ---------------- PERSISTENT combiner recurrence (H=1024) ----------------
// 128 blocks x 8 hidden-col slices. Whh_c slice (32 x 1024) resident in smem.
__global__ void __launch_bounds__(256) lstm_c_persist(
    const float* __restrict__ Whh, const float* __restrict__ bi, const float* __restrict__ bh) {
    extern __shared__ float sm[];
    float* Wt = sm;                  // [32][32][36]
    float* As = sm + 32 * 32 * 36;   // [2][256][36]
    float* gbuf = As;

    const int j0 = blockIdx.x * 8;
    const int tid = threadIdx.x;
    const int wm = tid >> 5;

#pragma unroll 1
    for (int i = 0; i < 32; i++) {
        int lin4 = i * 256 + tid;      // 8192 float4
        int r = lin4 >> 8;             // 256 float4 per row
        int c4 = (lin4 & 255) * 4;
        int gr = (r >> 3) * H2D + j0 + (r & 7);
        float4 v = *(const float4*)(Whh + (size_t)gr * H2D + c4);
        v.x = t32(v.x); v.y = t32(v.y); v.z = t32(v.z); v.w = t32(v.w);
        *(float4*)(Wt + (c4 >> 5) * 1152 + r * 36 + (c4 & 31)) = v;
    }
    const int jj = tid >> 5;
    const int brow = tid & 31;
    float bsum[4];
    const float* gp[4];
#pragma unroll
    for (int g = 0; g < 4; g++) {
        bsum[g] = bi[g * H2D + j0 + jj] + bh[g * H2D + j0 + jj];
        gp[g] = d_Gct + (size_t)(g * H2D + j0 + jj) * NROWS;
    }
    __syncthreads();

#pragma unroll 1
    for (int t = 0; t < SLEN; t++) {
        const float* hprev = d_hcb[t & 1];
        float* hnext = d_hcb[(t + 1) & 1];
        const int grow0 = t * BSZ;

        wmma::fragment<wmma::accumulator, 16, 16, 8, float> cf[2][2];
#pragma unroll
        for (int i = 0; i < 2; i++)
#pragma unroll
            for (int j = 0; j < 2; j++) wmma::fill_fragment(cf[i][j], 0.f);

        {
#pragma unroll
            for (int i = 0; i < 8; i++) {
                int lin4 = i * 256 + tid;
                int r = lin4 >> 3, c4 = (lin4 & 7) * 4;
                cp16(As + r * 36 + c4, hprev + (size_t)r * H2D + c4);
            }
            cp_commit();
        }
        int buf = 0;
#pragma unroll 1
        for (int kt = 0; kt < 32; kt++) {
            if (kt < 31) {
                int nb = buf ^ 1;
#pragma unroll
                for (int i = 0; i < 8; i++) {
                    int lin4 = i * 256 + tid;
                    int r = lin4 >> 3, c4 = (lin4 & 7) * 4;
                    cp16(As + nb * 9216 + r * 36 + c4,
                         hprev + (size_t)r * H2D + (kt + 1) * 32 + c4);
                }
                cp_commit();
                cp_wait<1>();
            } else {
                cp_wait<0>();
            }
            __syncthreads();
#pragma unroll
            for (int ks = 0; ks < 4; ks++) {
                wmma::fragment<wmma::matrix_a, 16, 16, 8, wmma::precision::tf32, wmma::row_major> af[2];
                wmma::fragment<wmma::matrix_b, 16, 16, 8, wmma::precision::tf32, wmma::col_major> bf[2];
#pragma unroll
                for (int i = 0; i < 2; i++)
                    wmma::load_matrix_sync(af[i], As + buf * 9216 + (wm * 32 + i * 16) * 36 + ks * 8, 36);
#pragma unroll
                for (int j = 0; j < 2; j++)
                    wmma::load_matrix_sync(bf[j], Wt + kt * 1152 + (j * 16) * 36 + ks * 8, 36);
#pragma unroll
                for (int i = 0; i < 2; i++)
#pragma unroll
                    for (int j = 0; j < 2; j++) wmma::mma_sync(cf[i][j], af[i], bf[j], cf[i][j]);
            }
            __syncthreads();
            buf ^= 1;
        }
#pragma unroll
        for (int i = 0; i < 2; i++)
#pragma unroll
            for (int j = 0; j < 2; j++)
                wmma::store_matrix_sync(gbuf + (wm * 32 + i * 16) * 36 + j * 16, cf[i][j], 36,
                                        wmma::mem_row_major);
        __syncthreads();
#pragma unroll
        for (int p = 0; p < 8; p++) {
            int b = p * 32 + brow;
            float gi = gbuf[b * 36 + jj]      + gp[0][grow0 + b] + bsum[0];
            float gf = gbuf[b * 36 + 8 + jj]  + gp[1][grow0 + b] + bsum[1];
            float gg = gbuf[b * 36 + 16 + jj] + gp[2][grow0 + b] + bsum[2];
            float go = gbuf[b * 36 + 24 + jj] + gp[3][grow0 + b] + bsum[3];
            float* cp_ = d_cc + (size_t)b * H2D + j0 + jj;
            float cn = sigm(gf) * cp_[0] + sigm(gi) * tanhf(gg);
            cp_[0] = cn;
            float hn = sigm(go) * tanhf(cn);
            hnext[(size_t)b * H2D + j0 + jj] = t32(hn);
            if (t == SLEN - 1) d_hcfull[(size_t)b * H2D + j0 + jj] = hn;  // full precision for head
        }
        if (t < SLEN - 1) grid_sync(128);
    }
}

// ---------------- head: 3xTF32 error-compensated GEMM (fp32-accurate) ----------------
__global__ void __launch_bounds__(256) head3_kernel(const float* __restrict__ A,
                                                    const float* __restrict__ W,
                                                    float* __restrict__ C) {
    extern __shared__ float sm[];
    float(*Ahi)[36] = (float(*)[36])sm;
    float(*Alo)[36] = (float(*)[36])(sm + 128 * 36);
    float(*Bhi)[36] = (float(*)[36])(sm + 2 * 128 * 36);
    float(*Blo)[36] = (float(*)[36])(sm + 3 * 128 * 36);
    const int K = H2D, N = VDIM;
    const int m0 = blockIdx.y * 128, n0 = blockIdx.x * 128;
    const int tid = threadIdx.x;
    const int w = tid >> 5, wm = w >> 1, wn = w & 1;

    wmma::fragment<wmma::accumulator, 16, 16, 8, float> cf[2][4];
#pragma unroll
    for (int i = 0; i < 2; i++)
#pragma unroll
        for (int j = 0; j < 4; j++) wmma::fill_fragment(cf[i][j], 0.f);

    for (int k0 = 0; k0 < K; k0 += 32) {
#pragma unroll
        for (int i = 0; i < 4; i++) {
            int lin = tid + i * 256;
            int r = lin >> 3, c4 = (lin & 7) * 4;
            float4 v = *(const float4*)(A + (size_t)(m0 + r) * K + k0 + c4);
            float4 hi, lo;
            hi.x = t32(v.x); lo.x = t32(v.x - hi.x);
            hi.y = t32(v.y); lo.y = t32(v.y - hi.y);
            hi.z = t32(v.z); lo.z = t32(v.z - hi.z);
            hi.w = t32(v.w); lo.w = t32(v.w - hi.w);
            *(float4*)(&Ahi[r][c4]) = hi;
            *(float4*)(&Alo[r][c4]) = lo;
        }
#pragma unroll
        for (int i = 0; i < 4; i++) {
            int lin = tid + i * 256;
            int r = lin >> 3, c4 = (lin & 7) * 4;
            float4 v = *(const float4*)(W + (size_t)(n0 + r) * K + k0 + c4);
            float4 hi, lo;
            hi.x = t32(v.x); lo.x = t32(v.x - hi.x);
            hi.y = t32(v.y); lo.y = t32(v.y - hi.y);
            hi.z = t32(v.z); lo.z = t32(v.z - hi.z);
            hi.w = t32(v.w); lo.w = t32(v.w - hi.w);
            *(float4*)(&Bhi[r][c4]) = hi;
            *(float4*)(&Blo[r][c4]) = lo;
        }
        __syncthreads();
#pragma unroll
        for (int ks = 0; ks < 4; ks++) {
            wmma::fragment<wmma::matrix_a, 16, 16, 8, wmma::precision::tf32, wmma::row_major> ah[2], al[2];
            wmma::fragment<wmma::matrix_b, 16, 16, 8, wmma::precision::tf32, wmma::col_major> bhf[4], blf[4];
#pragma unroll
            for (int i = 0; i < 2; i++) {
                wmma::load_matrix_sync(ah[i], &Ahi[wm * 32 + i * 16][ks * 8], 36);
                wmma::load_matrix_sync(al[i], &Alo[wm * 32 + i * 16][ks * 8], 36);
            }
#pragma unroll
            for (int j = 0; j < 4; j++) {
                wmma::load_matrix_sync(bhf[j], &Bhi[wn * 64 + j * 16][ks * 8], 36);
                wmma::load_matrix_sync(blf[j], &Blo[wn * 64 + j * 16][ks * 8], 36);
            }
#pragma unroll
            for (int i = 0; i < 2; i++)
#pragma unroll
                for (int j = 0; j < 4; j++) {
                    wmma::mma_sync(cf[i][j], al[i], bhf[j], cf[i][j]);
                    wmma::mma_sync(cf[i][j], ah[i], blf[j], cf[i][j]);
                    wmma::mma_sync(cf[i][j], ah[i], bhf[j], cf[i][j]);
                }
        }
        __syncthreads();
    }
#pragma unroll
    for (int i = 0; i < 2; i++)
#pragma unroll
        for (int j = 0; j < 4; j++)
            wmma::store_matrix_sync(C + (size_t)(m0 + wm * 32 + i * 16) * N + n0 + wn * 64 + j * 16,
                                    cf[i][j], N, wmma::mem_row_major);
}

__global__ void bias_add_kernel(float* __restrict__ C, const float* __restrict__ bout) {
    size_t idx = (size_t)blockIdx.x * 256 + threadIdx.x;
    float4 v = ((float4*)C)[idx];
    int n = (int)(idx % (VDIM / 4)) * 4;
    v.x += bout[n]; v.y += bout[n + 1]; v.z += bout[n + 2]; v.w += bout[n + 3];
    ((float4*)C)[idx] = v;
}

// ---------------- host orchestration ----------------
extern "C" void kernel_launch(void* const* d_in, const int* in_sizes, int n_in,
                              void* d_out, int out_size) {
    (void)in_sizes; (void)n_in; (void)out_size;
    const int* x = (const int*)d_in[0];
    const float* Wemb = (const float*)d_in[1];
    const float* WihF = (const float*)d_in[2];
    const float* WhhF = (const float*)d_in[3];
    const float* biF = (const float*)d_in[4];
    const float* bhF = (const float*)d_in[5];
    const float* WihB = (const float*)d_in[6];
    const float* WhhB = (const float*)d_in[7];
    const float* biB = (const float*)d_in[8];
    const float* bhB = (const float*)d_in[9];
    const float* WihC = (const float*)d_in[10];
    const float* WhhC = (const float*)d_in[11];
    const float* biC = (const float*)d_in[12];
    const float* bhC = (const float*)d_in[13];
    const float* Wout = (const float*)d_in[14];
    const float* bout = (const float*)d_in[15];
    const float* h0f = (const float*)d_in[16];
    const float* c0f = (const float*)d_in[17];
    const float* h0b = (const float*)d_in[18];
    const float* c0b = (const float*)d_in[19];
    const float* h0c = (const float*)d_in[20];
    const float* c0c = (const float*)d_in[21];
    float* out = (float*)d_out;

    void *pE, *pGft, *pGbt, *pCI, *pGct, *ph, *pc, *phc, *pcc, *phcf, *pWF, *pWB, *pWC;
    cudaGetSymbolAddress(&pE, d_E);
    cudaGetSymbolAddress(&pGft, d_Gft);
    cudaGetSymbolAddress(&pGbt, d_Gbt);
    cudaGetSymbolAddress(&pCI, d_CombIn);
    cudaGetSymbolAddress(&pGct, d_Gct);
    cudaGetSymbolAddress(&ph, d_h);
    cudaGetSymbolAddress(&pc, d_cfb);
    cudaGetSymbolAddress(&phc, d_hcb);
    cudaGetSymbolAddress(&pcc, d_cc);
    cudaGetSymbolAddress(&phcf, d_hcfull);
    cudaGetSymbolAddress(&pWF, d_WihFr);
    cudaGetSymbolAddress(&pWB, d_WihBr);
    cudaGetSymbolAddress(&pWC, d_WihCr);

    cudaFuncSetAttribute(gemm_pre, cudaFuncAttributeMaxDynamicSharedMemorySize, 73728);
    cudaFuncSetAttribute(lstm_fb_persist, cudaFuncAttributeMaxDynamicSharedMemorySize, 147456);
    cudaFuncSetAttribute(lstm_c_persist, cudaFuncAttributeMaxDynamicSharedMemorySize, 221184);
    cudaFuncSetAttribute(head3_kernel, cudaFuncAttributeMaxDynamicSharedMemorySize, 73728);

    const size_t HS = (size_t)BSZ * HDIM * sizeof(float);
    const size_t H2S = (size_t)BSZ * H2D * sizeof(float);

    // rounded weight copies for projection GEMMs
    roundcopy_kernel<<<(4 * HDIM * HDIM / 4 + 255) / 256, 256>>>((float*)pWF, WihF, 4 * HDIM * HDIM / 4);
    roundcopy_kernel<<<(4 * HDIM * HDIM / 4 + 255) / 256, 256>>>((float*)pWB, WihB, 4 * HDIM * HDIM / 4);
    roundcopy_kernel<<<(4 * H2D * H2D / 4 + 255) / 256, 256>>>((float*)pWC, WihC, 4 * H2D * H2D / 4);
    // rounded initial hidden states into parity-0 buffers
    roundcopy_kernel<<<(BSZ * HDIM / 4 + 255) / 256, 256>>>((float*)ph, h0f, BSZ * HDIM / 4);
    roundcopy_kernel<<<(BSZ * HDIM / 4 + 255) / 256, 256>>>((float*)ph + 2 * BSZ * HDIM, h0b, BSZ * HDIM / 4);
    roundcopy_kernel<<<(BSZ * H2D / 4 + 255) / 256, 256>>>((float*)phc, h0c, BSZ * H2D / 4);
    // fp32 cell states
    cudaMemcpyAsync(pc, c0f, HS, cudaMemcpyDeviceToDevice, 0);
    cudaMemcpyAsync((char*)pc + HS, c0b, HS, cudaMemcpyDeviceToDevice, 0);
    cudaMemcpyAsync(pcc, c0c, H2S, cudaMemcpyDeviceToDevice, 0);

    embed_kernel<<<NROWS, 128>>>(x, Wemb);
    // input projections, TRANSPOSED: Gt[gate_row][seq_row] = Wih @ E^T
    gemm_pre<<<dim3(NROWS / 128, (4 * HDIM) / 128), 256, 73728>>>((const float*)pWF, (const float*)pE,
                                                                  (float*)pGft, 4 * HDIM, NROWS, HDIM);
    gemm_pre<<<dim3(NROWS / 128, (4 * HDIM) / 128), 256, 73728>>>((const float*)pWB, (const float*)pE,
                                                                  (float*)pGbt, 4 * HDIM, NROWS, HDIM);
    // persistent fwd+bwd recurrence
    lstm_fb_persist<<<128, 256, 147456>>>(WhhF, WhhB, biF, bhF, biB, bhB);
    // combiner input projection (transposed), then persistent combiner recurrence
    gemm_pre<<<dim3(NROWS / 128, (4 * H2D) / 128), 256, 73728>>>((const float*)pWC, (const float*)pCI,
                                                                 (float*)pGct, 4 * H2D, NROWS, H2D);
    lstm_c_persist<<<128, 256, 221184>>>(WhhC, biC, bhC);
    // output head (3xTF32) + bias
    head3_kernel<<<dim3(VDIM / 128, BSZ / 128), 256, 73728>>>((const float*)phcf, Wout, out);
    bias_add_kernel<<<(BSZ * VDIM / 4) / 256, 256>>>(out, bout);
}

// round 3
// speedup vs baseline: 1.7817x; 1.7817x over previous
#include <cuda_runtime.h>
#include <mma.h>

using namespace nvcuda;

#define BSZ 256
#define SLEN 64
#define HDIM 512
#define H2D 1024
#define VDIM 32000
#define NROWS (BSZ * SLEN) /* 16384 */

// ---------------- device scratch (static, no allocations) ----------------
__device__ float d_E[(size_t)NROWS * HDIM];         // embeddings (tf32-rounded)
__device__ float d_Gf[(size_t)NROWS * 4 * HDIM];    // fwd input preacts [sample][2048]
__device__ float d_Gb[(size_t)NROWS * 4 * HDIM];    // bwd input preacts
__device__ float d_CombIn[(size_t)NROWS * H2D];     // [hf | hb] per (t,b), rounded
__device__ float d_Gc[(size_t)NROWS * 4 * H2D];     // combiner input preacts [sample][4096]
__device__ float d_h[2][2][BSZ * HDIM];             // [dir][parity], rounded
__device__ float d_cfb[2][BSZ * HDIM];              // [dir], fp32
__device__ float d_hcb[2][BSZ * H2D];               // combiner h [parity], rounded
__device__ float d_cc[BSZ * H2D];                   // fp32
__device__ float d_hcfull[BSZ * H2D];               // final combiner h, FULL fp32 (head input)
__device__ float d_WihFr[4 * HDIM * HDIM];          // tf32-rounded weight copies
__device__ float d_WihBr[4 * HDIM * HDIM];
__device__ float d_WihCr[(size_t)4 * H2D * H2D];
__device__ float d_WhhFr[4 * HDIM * HDIM];
__device__ float d_WhhBr[4 * HDIM * HDIM];
__device__ float d_WhhCr[(size_t)4 * H2D * H2D];

// round-to-nearest-even into tf32 (10 explicit mantissa bits)
__device__ __forceinline__ float t32(float x) {
    unsigned u = __float_as_uint(x);
    unsigned r = (u + 0xFFFu + ((u >> 13) & 1u)) & 0xFFFFE000u;
    return __uint_as_float(r);
}
__device__ __forceinline__ float sigm(float x) { return 1.f / (1.f + __expf(-x)); }

__device__ __forceinline__ void cp16(void* dst, const void* src) {
    unsigned d = (unsigned)__cvta_generic_to_shared(dst);
    asm volatile("cp.async.cg.shared.global [%0], [%1], 16;" ::"r"(d), "l"(src));
}
__device__ __forceinline__ void cp_commit() { asm volatile("cp.async.commit_group;"); }
template <int N>
__device__ __forceinline__ void cp_wait() { asm volatile("cp.async.wait_group %0;" ::"n"(N)); }

// ---------------- small prep kernels ----------------
__global__ void roundcopy_kernel(float* __restrict__ dst, const float* __restrict__ src, int n4) {
    int i = blockIdx.x * 256 + threadIdx.x;
    if (i < n4) {
        float4 v = ((const float4*)src)[i];
        v.x = t32(v.x); v.y = t32(v.y); v.z = t32(v.z); v.w = t32(v.w);
        ((float4*)dst)[i] = v;
    }
}

__global__ void embed_kernel(const int* __restrict__ x, const float* __restrict__ Wemb) {
    int r = blockIdx.x;
    int tok = x[r];
    float4* dst = (float4*)(d_E + (size_t)r * HDIM);
    if (tok == 0) {
        float4 z = {0.f, 0.f, 0.f, 0.f};
        dst[threadIdx.x] = z;
    } else {
        float4 v = ((const float4*)(Wemb + (size_t)tok * HDIM))[threadIdx.x];
        v.x = t32(v.x); v.y = t32(v.y); v.z = t32(v.z); v.w = t32(v.w);
        dst[threadIdx.x] = v;
    }
}

// ---------------- TF32 GEMM on PRE-ROUNDED operands, cp.async double-buffered ----------
// C[M,N] = A[M,K] @ W[N,K]^T. block tile 128x128, BK=32, 256 threads (8 warps 4x2)
__global__ void __launch_bounds__(256) gemm_pre(const float* __restrict__ A,
                                                const float* __restrict__ W,
                                                float* __restrict__ C,
                                                int M, int N, int K) {
    extern __shared__ float sm[];
    float* As = sm;                 // [2][128][36]
    float* Bs = sm + 2 * 128 * 36;  // [2][128][36]
    const int m0 = blockIdx.y * 128, n0 = blockIdx.x * 128;
    const int tid = threadIdx.x;
    const int w = tid >> 5, wm = w >> 1, wn = w & 1;
    const int KT = K >> 5;

    wmma::fragment<wmma::accumulator, 16, 16, 8, float> cf[2][4];
#pragma unroll
    for (int i = 0; i < 2; i++)
#pragma unroll
        for (int j = 0; j < 4; j++) wmma::fill_fragment(cf[i][j], 0.f);

    {
#pragma unroll
        for (int i = 0; i < 4; i++) {
            int lin = tid + i * 256;
            int r = lin >> 3, c4 = (lin & 7) * 4;
            cp16(As + r * 36 + c4, A + (size_t)(m0 + r) * K + c4);
            cp16(Bs + r * 36 + c4, W + (size_t)(n0 + r) * K + c4);
        }
        cp_commit();
    }
    int buf = 0;
#pragma unroll 1
    for (int kt = 0; kt < KT; kt++) {
        if (kt + 1 < KT) {
            int nb = buf ^ 1;
#pragma unroll
            for (int i = 0; i < 4; i++) {
                int lin = tid + i * 256;
                int r = lin >> 3, c4 = (lin & 7) * 4;
                cp16(As + nb * 4608 + r * 36 + c4, A + (size_t)(m0 + r) * K + (kt + 1) * 32 + c4);
                cp16(Bs + nb * 4608 + r * 36 + c4, W + (size_t)(n0 + r) * K + (kt + 1) * 32 + c4);
            }
            cp_commit();
            cp_wait<1>();
        } else {
            cp_wait<0>();
        }
        __syncthreads();
#pragma unroll
        for (int ks = 0; ks < 4; ks++) {
            wmma::fragment<wmma::matrix_a, 16, 16, 8, wmma::precision::tf32, wmma::row_major> af[2];
            wmma::fragment<wmma::matrix_b, 16, 16, 8, wmma::precision::tf32, wmma::col_major> bf[4];
#pragma unroll
            for (int i = 0; i < 2; i++)
                wmma::load_matrix_sync(af[i], As + buf * 4608 + (wm * 32 + i * 16) * 36 + ks * 8, 36);
#pragma unroll
            for (int j = 0; j < 4; j++)
                wmma::load_matrix_sync(bf[j], Bs + buf * 4608 + (wn * 64 + j * 16) * 36 + ks * 8, 36);
#pragma unroll
            for (int i = 0; i < 2; i++)
#pragma unroll
                for (int j = 0; j < 4; j++) wmma::mma_sync(cf[i][j], af[i], bf[j], cf[i][j]);
        }
        __syncthreads();
        buf ^= 1;
    }
#pragma unroll
    for (int i = 0; i < 2; i++)
#pragma unroll
        for (int j = 0; j < 4; j++)
            wmma::store_matrix_sync(C + (size_t)(m0 + wm * 32 + i * 16) * N + n0 + wn * 64 + j * 16,
                                    cf[i][j], N, wmma::mem_row_major);
}

// ---------------- fused LSTM step, fwd+bwd, double-buffered ----------------
// grid (8, 16, 2): 32-batch x 32-hid tiles. 256 threads, warps 2(m) x 4(n).
// smem: As[2][32][36] + Bs[2][128][36] = 46080 B -> ~5 CTAs/SM
__global__ void __launch_bounds__(256) lstm_step_fb(
    const float* __restrict__ WhhF, const float* __restrict__ WhhB,
    const float* __restrict__ biF, const float* __restrict__ bhF,
    const float* __restrict__ biB, const float* __restrict__ bhB, int t) {
    extern __shared__ float sm[];
    float* As = sm;                 // [2][32][36]
    float* Bs = sm + 2 * 32 * 36;   // [2][128][36]
    float* gbuf = sm;               // overlay [32][132] after K loop

    const int dir = blockIdx.z;
    const float* Whh = dir ? WhhB : WhhF;
    const float* bi = dir ? biB : biF;
    const float* bh = dir ? bhB : bhF;
    const float* hprev = d_h[dir][t & 1];
    float* hnext = d_h[dir][(t + 1) & 1];
    float* cst = d_cfb[dir];
    const float* G = dir ? d_Gb : d_Gf;
    const int grow0 = (dir ? (SLEN - 1 - t) : t) * BSZ;

    const int m0 = blockIdx.x * 32;
    const int j0 = blockIdx.y * 32;
    const int tid = threadIdx.x;
    const int w = tid >> 5, wm = w >> 2, wn = w & 3;

    wmma::fragment<wmma::accumulator, 16, 16, 8, float> cf[2];
    wmma::fill_fragment(cf[0], 0.f);
    wmma::fill_fragment(cf[1], 0.f);

    // prologue: prefetch chunk 0
    {
        int r = tid >> 3, c4 = (tid & 7) * 4;
        cp16(As + r * 36 + c4, hprev + (size_t)(m0 + r) * HDIM + c4);
#pragma unroll
        for (int i = 0; i < 4; i++) {
            int lin = tid + i * 256;
            int rr = lin >> 3, cc = (lin & 7) * 4;
            int gr = (rr >> 5) * HDIM + j0 + (rr & 31);
            cp16(Bs + rr * 36 + cc, Whh + (size_t)gr * HDIM + cc);
        }
        cp_commit();
    }
    int buf = 0;
#pragma unroll 1
    for (int kt = 0; kt < 16; kt++) {
        if (kt < 15) {
            int nb = buf ^ 1;
            int r = tid >> 3, c4 = (tid & 7) * 4;
            cp16(As + nb * 1152 + r * 36 + c4, hprev + (size_t)(m0 + r) * HDIM + (kt + 1) * 32 + c4);
#pragma unroll
            for (int i = 0; i < 4; i++) {
                int lin = tid + i * 256;
                int rr = lin >> 3, cc = (lin & 7) * 4;
                int gr = (rr >> 5) * HDIM + j0 + (rr & 31);
                cp16(Bs + nb * 4608 + rr * 36 + cc, Whh + (size_t)gr * HDIM + (kt + 1) * 32 + cc);
            }
            cp_commit();
            cp_wait<1>();
        } else {
            cp_wait<0>();
        }
        __syncthreads();
#pragma unroll
        for (int ks = 0; ks < 4; ks++) {
            wmma::fragment<wmma::matrix_a, 16, 16, 8, wmma::precision::tf32, wmma::row_major> af;
            wmma::fragment<wmma::matrix_b, 16, 16, 8, wmma::precision::tf32, wmma::col_major> bf[2];
            wmma::load_matrix_sync(af, As + buf * 1152 + (wm * 16) * 36 + ks * 8, 36);
#pragma unroll
            for (int j = 0; j < 2; j++)
                wmma::load_matrix_sync(bf[j], Bs + buf * 4608 + (wn * 32 + j * 16) * 36 + ks * 8, 36);
#pragma unroll
            for (int j = 0; j < 2; j++) wmma::mma_sync(cf[j], af, bf[j], cf[j]);
        }
        __syncthreads();
        buf ^= 1;
    }
#pragma unroll
    for (int j = 0; j < 2; j++)
        wmma::store_matrix_sync(gbuf + (wm * 16) * 132 + wn * 32 + j * 16, cf[j], 132,
                                wmma::mem_row_major);
    __syncthreads();

#pragma unroll
    for (int p = 0; p < 4; p++) {  // 32x32 cell elements, fully coalesced over lanes
        int idx = p * 256 + tid;
        int m = idx >> 5, jj = idx & 31;
        int b = m0 + m, j = j0 + jj;
        const float* grow = G + (size_t)(grow0 + b) * (4 * HDIM);
        float ip = gbuf[m * 132 + jj]      + grow[j]            + bi[j]            + bh[j];
        float fp = gbuf[m * 132 + 32 + jj] + grow[HDIM + j]     + bi[HDIM + j]     + bh[HDIM + j];
        float gp = gbuf[m * 132 + 64 + jj] + grow[2 * HDIM + j] + bi[2 * HDIM + j] + bh[2 * HDIM + j];
        float op = gbuf[m * 132 + 96 + jj] + grow[3 * HDIM + j] + bi[3 * HDIM + j] + bh[3 * HDIM + j];
        float cn = sigm(fp) * cst[(size_t)b * HDIM + j] + sigm(ip) * tanhf(gp);
        cst[(size_t)b * HDIM + j] = cn;
        float hr = t32(sigm(op) * tanhf(cn));
        hnext[(size_t)b * HDIM + j] = hr;
        d_CombIn[(size_t)(t * BSZ + b) * H2D + dir * HDIM + j] = hr;
    }
}

// ---------------- fused combiner LSTM step (H=1024), double-buffered ----------------
// grid (8, 32): 32-batch x 32-hid tiles, K=1024 (32 chunks)
__global__ void __launch_bounds__(256) lstm_step_c(
    const float* __restrict__ Whh, const float* __restrict__ bi,
    const float* __restrict__ bh, int t) {
    extern __shared__ float sm[];
    float* As = sm;
    float* Bs = sm + 2 * 32 * 36;
    float* gbuf = sm;

    const float* hprev = d_hcb[t & 1];
    float* hnext = d_hcb[(t + 1) & 1];
    const int grow0 = t * BSZ;

    const int m0 = blockIdx.x * 32;
    const int j0 = blockIdx.y * 32;
    const int tid = threadIdx.x;
    const int w = tid >> 5, wm = w >> 2, wn = w & 3;

    wmma::fragment<wmma::accumulator, 16, 16, 8, float> cf[2];
    wmma::fill_fragment(cf[0], 0.f);
    wmma::fill_fragment(cf[1], 0.f);

    {
        int r = tid >> 3, c4 = (tid & 7) * 4;
        cp16(As + r * 36 + c4, hprev + (size_t)(m0 + r) * H2D + c4);
#pragma unroll
        for (int i = 0; i < 4; i++) {
            int lin = tid + i * 256;
            int rr = lin >> 3, cc = (lin & 7) * 4;
            int gr = (rr >> 5) * H2D + j0 + (rr & 31);
            cp16(Bs + rr * 36 + cc, Whh + (size_t)gr * H2D + cc);
        }
        cp_commit();
    }
    int buf = 0;
#pragma unroll 1
    for (int kt = 0; kt < 32; kt++) {
        if (kt < 31) {
            int nb = buf ^ 1;
            int r = tid >> 3, c4 = (tid & 7) * 4;
            cp16(As + nb * 1152 + r * 36 + c4, hprev + (size_t)(m0 + r) * H2D + (kt + 1) * 32 + c4);
#pragma unroll
            for (int i = 0; i < 4; i++) {
                int lin = tid + i * 256;
                int rr = lin >> 3, cc = (lin & 7) * 4;
                int gr = (rr >> 5) * H2D + j0 + (rr & 31);
                cp16(Bs + nb * 4608 + rr * 36 + cc, Whh + (size_t)gr * H2D + (kt + 1) * 32 + cc);
            }
            cp_commit();
            cp_wait<1>();
        } else {
            cp_wait<0>();
        }
        __syncthreads();
#pragma unroll
        for (int ks = 0; ks < 4; ks++) {
            wmma::fragment<wmma::matrix_a, 16, 16, 8, wmma::precision::tf32, wmma::row_major> af;
            wmma::fragment<wmma::matrix_b, 16, 16, 8, wmma::precision::tf32, wmma::col_major> bf[2];
            wmma::load_matrix_sync(af, As + buf * 1152 + (wm * 16) * 36 + ks * 8, 36);
#pragma unroll
            for (int j = 0; j < 2; j++)
                wmma::load_matrix_sync(bf[j], Bs + buf * 4608 + (wn * 32 + j * 16) * 36 + ks * 8, 36);
#pragma unroll
            for (int j = 0; j < 2; j++) wmma::mma_sync(cf[j], af, bf[j], cf[j]);
        }
        __syncthreads();
        buf ^= 1;
    }
#pragma unroll
    for (int j = 0; j < 2; j++)
        wmma::store_matrix_sync(gbuf + (wm * 16) * 132 + wn * 32 + j * 16, cf[j], 132,
                                wmma::mem_row_major);
    __syncthreads();

#pragma unroll
    for (int p = 0; p < 4; p++) {
        int idx = p * 256 + tid;
        int m = idx >> 5, jj = idx & 31;
        int b = m0 + m, j = j0 + jj;
        const float* grow = d_Gc + (size_t)(grow0 + b) * (4 * H2D);
        float ip = gbuf[m * 132 + jj]      + grow[j]           + bi[j]           + bh[j];
        float fp = gbuf[m * 132 + 32 + jj] + grow[H2D + j]     + bi[H2D + j]     + bh[H2D + j];
        float gp = gbuf[m * 132 + 64 + jj] + grow[2 * H2D + j] + bi[2 * H2D + j] + bh[2 * H2D + j];
        float op = gbuf[m * 132 + 96 + jj] + grow[3 * H2D + j] + bi[3 * H2D + j] + bh[3 * H2D + j];
        float cn = sigm(fp) * d_cc[(size_t)b * H2D + j] + sigm(ip) * tanhf(gp);
        d_cc[(size_t)b * H2D + j] = cn;
        float hn = sigm(op) * tanhf(cn);
        hnext[(size_t)b * H2D + j] = t32(hn);
        if (t == SLEN - 1) d_hcfull[(size_t)b * H2D + j] = hn;
    }
}

// ---------------- head: 3xTF32 error-compensated GEMM (fp32-accurate) ----------------
__global__ void __launch_bounds__(256) head3_kernel(const float* __restrict__ A,
                                                    const float* __restrict__ W,
                                                    float* __restrict__ C) {
    extern __shared__ float sm[];
    float(*Ahi)[36] = (float(*)[36])sm;
    float(*Alo)[36] = (float(*)[36])(sm + 128 * 36);
    float(*Bhi)[36] = (float(*)[36])(sm + 2 * 128 * 36);
    float(*Blo)[36] = (float(*)[36])(sm + 3 * 128 * 36);
    const int K = H2D, N = VDIM;
    const int m0 = blockIdx.y * 128, n0 = blockIdx.x * 128;
    const int tid = threadIdx.x;
    const int w = tid >> 5, wm = w >> 1, wn = w & 1;

    wmma::fragment<wmma::accumulator, 16, 16, 8, float> cf[2][4];
#pragma unroll
    for (int i = 0; i < 2; i++)
#pragma unroll
        for (int j = 0; j < 4; j++) wmma::fill_fragment(cf[i][j], 0.f);

    for (int k0 = 0; k0 < K; k0 += 32) {
#pragma unroll
        for (int i = 0; i < 4; i++) {
            int lin = tid + i * 256;
            int r = lin >> 3, c4 = (lin & 7) * 4;
            float4 v = *(const float4*)(A + (size_t)(m0 + r) * K + k0 + c4);
            float4 hi, lo;
            hi.x = t32(v.x); lo.x = t32(v.x - hi.x);
            hi.y = t32(v.y); lo.y = t32(v.y - hi.y);
            hi.z = t32(v.z); lo.z = t32(v.z - hi.z);
            hi.w = t32(v.w); lo.w = t32(v.w - hi.w);
            *(float4*)(&Ahi[r][c4]) = hi;
            *(float4*)(&Alo[r][c4]) = lo;
        }
#pragma unroll
        for (int i = 0; i < 4; i++) {
            int lin = tid + i * 256;
            int r = lin >> 3, c4 = (lin & 7) * 4;
            float4 v = *(const float4*)(W + (size_t)(n0 + r) * K + k0 + c4);
            float4 hi, lo;
            hi.x = t32(v.x); lo.x = t32(v.x - hi.x);
            hi.y = t32(v.y); lo.y = t32(v.y - hi.y);
            hi.z = t32(v.z); lo.z = t32(v.z - hi.z);
            hi.w = t32(v.w); lo.w = t32(v.w - hi.w);
            *(float4*)(&Bhi[r][c4]) = hi;
            *(float4*)(&Blo[r][c4]) = lo;
        }
        __syncthreads();
#pragma unroll
        for (int ks = 0; ks < 4; ks++) {
            wmma::fragment<wmma::matrix_a, 16, 16, 8, wmma::precision::tf32, wmma::row_major> ah[2], al[2];
            wmma::fragment<wmma::matrix_b, 16, 16, 8, wmma::precision::tf32, wmma::col_major> bhf[4], blf[4];
#pragma unroll
            for (int i = 0; i < 2; i++) {
                wmma::load_matrix_sync(ah[i], &Ahi[wm * 32 + i * 16][ks * 8], 36);
                wmma::load_matrix_sync(al[i], &Alo[wm * 32 + i * 16][ks * 8], 36);
            }
#pragma unroll
            for (int j = 0; j < 4; j++) {
                wmma::load_matrix_sync(bhf[j], &Bhi[wn * 64 + j * 16][ks * 8], 36);
                wmma::load_matrix_sync(blf[j], &Blo[wn * 64 + j * 16][ks * 8], 36);
            }
#pragma unroll
            for (int i = 0; i < 2; i++)
#pragma unroll
                for (int j = 0; j < 4; j++) {
                    wmma::mma_sync(cf[i][j], al[i], bhf[j], cf[i][j]);
                    wmma::mma_sync(cf[i][j], ah[i], blf[j], cf[i][j]);
                    wmma::mma_sync(cf[i][j], ah[i], bhf[j], cf[i][j]);
                }
        }
        __syncthreads();
    }
#pragma unroll
    for (int i = 0; i < 2; i++)
#pragma unroll
        for (int j = 0; j < 4; j++)
            wmma::store_matrix_sync(C + (size_t)(m0 + wm * 32 + i * 16) * N + n0 + wn * 64 + j * 16,
                                    cf[i][j], N, wmma::mem_row_major);
}

__global__ void bias_add_kernel(float* __restrict__ C, const float* __restrict__ bout) {
    size_t idx = (size_t)blockIdx.x * 256 + threadIdx.x;
    float4 v = ((float4*)C)[idx];
    int n = (int)(idx % (VDIM / 4)) * 4;
    v.x += bout[n]; v.y += bout[n + 1]; v.z += bout[n + 2]; v.w += bout[n + 3];
    ((float4*)C)[idx] = v;
}

// ---------------- host orchestration ----------------
extern "C" void kernel_launch(void* const* d_in, const int* in_sizes, int n_in,
                              void* d_out, int out_size) {
    (void)in_sizes; (void)n_in; (void)out_size;
    const int* x = (const int*)d_in[0];
    const float* Wemb = (const float*)d_in[1];
    const float* WihF = (const float*)d_in[2];
    const float* WhhF = (const float*)d_in[3];
    const float* biF = (const float*)d_in[4];
    const float* bhF = (const float*)d_in[5];
    const float* WihB = (const float*)d_in[6];
    const float* WhhB = (const float*)d_in[7];
    const float* biB = (const float*)d_in[8];
    const float* bhB = (const float*)d_in[9];
    const float* WihC = (const float*)d_in[10];
    const float* WhhC = (const float*)d_in[11];
    const float* biC = (const float*)d_in[12];
    const float* bhC = (const float*)d_in[13];
    const float* Wout = (const float*)d_in[14];
    const float* bout = (const float*)d_in[15];
    const float* h0f = (const float*)d_in[16];
    const float* c0f = (const float*)d_in[17];
    const float* h0b = (const float*)d_in[18];
    const float* c0b = (const float*)d_in[19];
    const float* h0c = (const float*)d_in[20];
    const float* c0c = (const float*)d_in[21];
    float* out = (float*)d_out;

    void *pE, *pGf, *pGb, *pCI, *pGc, *ph, *pc, *phc, *pcc, *phcf;
    void *pWiF, *pWiB, *pWiC, *pWhF, *pWhB, *pWhC;
    cudaGetSymbolAddress(&pE, d_E);
    cudaGetSymbolAddress(&pGf, d_Gf);
    cudaGetSymbolAddress(&pGb, d_Gb);
    cudaGetSymbolAddress(&pCI, d_CombIn);
    cudaGetSymbolAddress(&pGc, d_Gc);
    cudaGetSymbolAddress(&ph, d_h);
    cudaGetSymbolAddress(&pc, d_cfb);
    cudaGetSymbolAddress(&phc, d_hcb);
    cudaGetSymbolAddress(&pcc, d_cc);
    cudaGetSymbolAddress(&phcf, d_hcfull);
    cudaGetSymbolAddress(&pWiF, d_WihFr);
    cudaGetSymbolAddress(&pWiB, d_WihBr);
    cudaGetSymbolAddress(&pWiC, d_WihCr);
    cudaGetSymbolAddress(&pWhF, d_WhhFr);
    cudaGetSymbolAddress(&pWhB, d_WhhBr);
    cudaGetSymbolAddress(&pWhC, d_WhhCr);

    cudaFuncSetAttribute(gemm_pre, cudaFuncAttributeMaxDynamicSharedMemorySize, 73728);
    cudaFuncSetAttribute(head3_kernel, cudaFuncAttributeMaxDynamicSharedMemorySize, 73728);

    const size_t HS = (size_t)BSZ * HDIM * sizeof(float);
    const size_t H2S = (size_t)BSZ * H2D * sizeof(float);
    const int W1 = 4 * HDIM * HDIM / 4;          // float4 counts
    const int WC = 4 * H2D * H2D / 4;

    // tf32-rounded copies of all GEMM weight operands
    roundcopy_kernel<<<(W1 + 255) / 256, 256>>>((float*)pWiF, WihF, W1);
    roundcopy_kernel<<<(W1 + 255) / 256, 256>>>((float*)pWiB, WihB, W1);
    roundcopy_kernel<<<(WC + 255) / 256, 256>>>((float*)pWiC, WihC, WC);
    roundcopy_kernel<<<(W1 + 255) / 256, 256>>>((float*)pWhF, WhhF, W1);
    roundcopy_kernel<<<(W1 + 255) / 256, 256>>>((float*)pWhB, WhhB, W1);
    roundcopy_kernel<<<(WC + 255) / 256, 256>>>((float*)pWhC, WhhC, WC);
    // rounded initial hidden states into parity-0 buffers
    roundcopy_kernel<<<(BSZ * HDIM / 4 + 255) / 256, 256>>>((float*)ph, h0f, BSZ * HDIM / 4);
    roundcopy_kernel<<<(BSZ * HDIM / 4 + 255) / 256, 256>>>((float*)ph + 2 * BSZ * HDIM, h0b,
                                                            BSZ * HDIM / 4);
    roundcopy_kernel<<<(BSZ * H2D / 4 + 255) / 256, 256>>>((float*)phc, h0c, BSZ * H2D / 4);
    // fp32 cell states
    cudaMemcpyAsync(pc, c0f, HS, cudaMemcpyDeviceToDevice, 0);
    cudaMemcpyAsync((char*)pc + HS, c0b, HS, cudaMemcpyDeviceToDevice, 0);
    cudaMemcpyAsync(pcc, c0c, H2S, cudaMemcpyDeviceToDevice, 0);

    embed_kernel<<<NROWS, 128>>>(x, Wemb);
    // input projections: G[sample][4H] = E @ Wih^T
    gemm_pre<<<dim3((4 * HDIM) / 128, NROWS / 128), 256, 73728>>>(
        (const float*)pE, (const float*)pWiF, (float*)pGf, NROWS, 4 * HDIM, HDIM);
    gemm_pre<<<dim3((4 * HDIM) / 128, NROWS / 128), 256, 73728>>>(
        (const float*)pE, (const float*)pWiB, (float*)pGb, NROWS, 4 * HDIM, HDIM);
    // fwd + bwd recurrence, double-buffered step kernels
    for (int t = 0; t < SLEN; t++)
        lstm_step_fb<<<dim3(BSZ / 32, HDIM / 32, 2), 256, 46080>>>(
            (const float*)pWhF, (const float*)pWhB, biF, bhF, biB, bhB, t);
    // combiner input projection + recurrence
    gemm_pre<<<dim3((4 * H2D) / 128, NROWS / 128), 256, 73728>>>(
        (const float*)pCI, (const float*)pWiC, (float*)pGc, NROWS, 4 * H2D, H2D);
    for (int t = 0; t < SLEN; t++)
        lstm_step_c<<<dim3(BSZ / 32, H2D / 32), 256, 46080>>>((const float*)pWhC, biC, bhC, t);
    // output head (3xTF32) + bias
    head3_kernel<<<dim3(VDIM / 128, BSZ / 128), 256, 73728>>>((const float*)phcf, Wout, out);
    bias_add_kernel<<<(BSZ * VDIM / 4) / 256, 256>>>(out, bout);
}